// round 16
// baseline (speedup 1.0000x reference)
#include <cuda_runtime.h>
#include <cuda_bf16.h>
#include <cstdint>

// Shapes (fixed by the problem)
#define BB      8
#define TIMES   288
#define NNODES  207
#define DD      64
#define TT      288
#define NBT     (BB * TIMES)      // 2304 (b,t) rows
#define HALF    (NBT / 2)         // 1152 blocks = single wave at occ 8 (<=1184)
#define NV      (NNODES * DD / 4) // 3312 float4 per row
#define REM4    (NV - 12 * 256)   // 240-thread remainder

// R16: single-wave grid (1152 blocks, each 2 rows -> no wave transition, no
// wave-2 spread; all blocks identical cost) + fully-unrolled interleaved
// store stream (2 x (12+1) STG.128 per thread, alternating rows for double
// MLP and L2-slice spread). Plain STG.128 = best measured store path.
__global__ __launch_bounds__(256, 8)
void tememb_kernel(const int*   __restrict__ TE,
                   const float* __restrict__ W1,
                   const float* __restrict__ b1,
                   const float* __restrict__ W2,
                   const float* __restrict__ b2,
                   float*       __restrict__ out)
{
    const int tid  = threadIdx.x;          // 0..255
    const int bt0  = blockIdx.x;           // 0..1151
    const int bt1  = blockIdx.x + HALF;    // 1152..2303
    const int grp  = tid >> 6;             // 0..3
    const int lane = tid & 63;

    __shared__ float h[2][DD];
    __shared__ float o[2][DD];

    // ---- prologue: groups 0 and 1 each compute one row's MLP ----
    if (grp < 2) {
        const int bt = (grp == 0) ? bt0 : bt1;
        const int* te = TE + (size_t)bt * (NNODES * 2);   // node 0 of (b,t)
        int dow = te[0] % 7;  if (dow < 0) dow += 7;
        int tod = te[1] % TT; if (tod < 0) tod += TT;
        // one_hot(dow,7) ++ one_hot(tod,288) @ W1  ==  W1[dow] + W1[7+tod]
        float v = W1[dow * DD + lane] + W1[(7 + tod) * DD + lane] + b1[lane];
        h[grp][lane] = v > 0.f ? v : 0.f;
    }
    __syncthreads();

    if (grp < 2) {
        float acc = b2[lane];
        #pragma unroll
        for (int d = 0; d < DD; ++d)
            acc = fmaf(h[grp][d], W2[d * DD + lane], acc);  // coalesced W2 columns
        o[grp][lane] = acc;
    }
    __syncthreads();

    // (tid + k*256) % 16 == tid % 16 -> fixed source float4 per thread.
    const float4 v0 = reinterpret_cast<const float4*>(o[0])[tid & 15];
    const float4 v1 = reinterpret_cast<const float4*>(o[1])[tid & 15];

    float4* __restrict__ d0 = reinterpret_cast<float4*>(out) + (size_t)bt0 * NV + tid;
    float4* __restrict__ d1 = reinterpret_cast<float4*>(out) + (size_t)bt1 * NV + tid;

    // Fully unrolled, interleaved: 26 back-to-back STG.128 per thread.
    #pragma unroll
    for (int k = 0; k < 12; ++k) {
        d0[(size_t)k * 256] = v0;
        d1[(size_t)k * 256] = v1;
    }
    if (tid < REM4) {
        d0[(size_t)12 * 256] = v0;
        d1[(size_t)12 * 256] = v1;
    }
}

extern "C" void kernel_launch(void* const* d_in, const int* in_sizes, int n_in,
                              void* d_out, int out_size)
{
    const int*   TE = (const int*)  d_in[0];
    const float* W1 = (const float*)d_in[1];
    const float* b1 = (const float*)d_in[2];
    const float* W2 = (const float*)d_in[3];
    const float* b2 = (const float*)d_in[4];
    float* out = (float*)d_out;

    tememb_kernel<<<HALF, 256>>>(TE, W1, b1, W2, b2, out);
}

// round 17
// speedup vs baseline: 1.0403x; 1.0403x over previous
#include <cuda_runtime.h>
#include <cuda_bf16.h>
#include <cstdint>

// Shapes (fixed by the problem)
#define BB      8
#define TIMES   288
#define NNODES  207
#define DD      64
#define TT      288
#define NBT     (BB * TIMES)      // 2304 (b,t) rows
#define NV8     (NNODES * DD / 8) // 1656 x 32B stores per row
#define REM8    (NV8 - 6 * 256)   // 120-thread remainder

// R17: last untested cell of the store matrix — 256-bit stores, NO eviction
// hint, fully unrolled. 256-bit halves L1 wavefront count (L1 has been the
// top mem% every round) without the L2 hint-state overhead that made the
// evict variants slower than plain 128-bit. 6 + 1 predicated back-to-back
// st.global.v8.b32 per thread; grid = 2304 one-row blocks (best measured).
struct v8 { uint32_t r[8]; };

__device__ __forceinline__ void st_v8(void* p, const v8& v) {
    asm volatile("st.global.v8.b32 [%0], {%1,%2,%3,%4,%5,%6,%7,%8};"
                 :: "l"(p), "r"(v.r[0]), "r"(v.r[1]), "r"(v.r[2]), "r"(v.r[3]),
                    "r"(v.r[4]), "r"(v.r[5]), "r"(v.r[6]), "r"(v.r[7]) : "memory");
}

__global__ __launch_bounds__(256, 8)
void tememb_kernel(const int*   __restrict__ TE,
                   const float* __restrict__ W1,
                   const float* __restrict__ b1,
                   const float* __restrict__ W2,
                   const float* __restrict__ b2,
                   float*       __restrict__ out)
{
    const int bt  = blockIdx.x;     // 0 .. 2303
    const int tid = threadIdx.x;    // 0 .. 255

    __shared__ float h[DD];
    __shared__ float o[DD];

    // TE is (B, TIMES, N, 2); only node 0 matters (reference slices [:, :, 0, :]).
    const int* te = TE + (size_t)bt * (NNODES * 2);

    if (tid < DD) {
        int dow = te[0] % 7;  if (dow < 0) dow += 7;
        int tod = te[1] % TT; if (tod < 0) tod += TT;
        // one_hot(dow,7) ++ one_hot(tod,288) @ W1  ==  W1[dow] + W1[7+tod]
        float v = W1[dow * DD + tid] + W1[(7 + tod) * DD + tid] + b1[tid];
        h[tid] = v > 0.f ? v : 0.f;
    }
    __syncthreads();

    if (tid < DD) {
        float acc = b2[tid];
        #pragma unroll
        for (int d = 0; d < DD; ++d)
            acc = fmaf(h[d], W2[d * DD + tid], acc);   // coalesced W2 columns
        o[tid] = acc;
    }
    __syncthreads();

    // (j*8) % 64 == (tid&7)*8 for j = tid + k*256 -> fixed 32B source slice.
    v8 val;
    {
        const uint32_t* os = reinterpret_cast<const uint32_t*>(o) + (tid & 7) * 8;
        #pragma unroll
        for (int i = 0; i < 8; ++i) val.r[i] = os[i];
    }

    uint32_t* __restrict__ base =
        reinterpret_cast<uint32_t*>(out) + (size_t)bt * (NNODES * DD) + (size_t)tid * 8;

    // 1656 stores / 256 threads: 6 full rounds + 120-thread remainder.
    #pragma unroll
    for (int k = 0; k < 6; ++k)
        st_v8(base + (size_t)k * 2048, val);
    if (tid < REM8)
        st_v8(base + (size_t)6 * 2048, val);
}

extern "C" void kernel_launch(void* const* d_in, const int* in_sizes, int n_in,
                              void* d_out, int out_size)
{
    const int*   TE = (const int*)  d_in[0];
    const float* W1 = (const float*)d_in[1];
    const float* b1 = (const float*)d_in[2];
    const float* W2 = (const float*)d_in[3];
    const float* b2 = (const float*)d_in[4];
    float* out = (float*)d_out;

    tememb_kernel<<<NBT, 256>>>(TE, W1, b1, W2, b2, out);
}